// round 13
// baseline (speedup 1.0000x reference)
#include <cuda_runtime.h>

// BinaryMaskEdgeSmoothing, R13: warp-autonomous cp.async pipelines.
//
// R9-R12 all plateau at DRAM ~74% with NOTHING saturated. The invariant is
// the block-wide barrier every row-pair: 8 warps convoy on wait+syncthreads,
// synchronizing their memory-quiet phases. Fix: make the smem ring
// warp-private (each warp's slot carries its own halo columns, fetched by
// lanes 0/1 via 4B cp.async) so consumers only need __syncwarp(). Warps
// slide independently; the SM's load pipe streams instead of oscillating.
//
// Rule (verified rel_err = 0.0 since R4; binary inputs make sum9 and
// gsum = 16*blur exact small ints in f32):
//     out = (gsum >= 9) || (gsum == 8 && cen == 1 && sum9 >= 4)
// via: qual = 6*cen + sum9; adj = qual>9.5 ? 0.6 : 0; out = gsum+adj > 8.5.

#define IMG_W   1024
#define IMG_H   1024
#define RPB     16                 // output rows per block
#define THREADS 256                // 8 warps x 128 cols each
#define NPAIRS  ((RPB + 2) / 2)    // 9 input pairs: rows r0-1 .. r0+RPB
#define ROWF    132                // floats per warp-row slot: 128 main + L + R + pad
#define WSLOT_B (ROWF * 4)         // 528
#define ROW_B   (8 * WSLOT_B)      // 4224 (8 warps)
#define PAIR_B  (2 * ROW_B)        // 8448

struct Sums { float t[4], g[4]; };

#define CP_COMMIT() asm volatile("cp.async.commit_group;")
#define CP_WAIT2()  asm volatile("cp.async.wait_group 2;")

__device__ __forceinline__ void cp16(unsigned dst, const float* src) {
    asm volatile("cp.async.cg.shared.global [%0], [%1], 16;" ::
                 "r"(dst), "l"(src));
}
__device__ __forceinline__ void cp4(unsigned dst, const float* src) {
    asm volatile("cp.async.ca.shared.global [%0], [%1], 4;" ::
                 "r"(dst), "l"(src));
}

// Consumer: warp-private row slot. rp[0..127] main, rp[128] left halo col,
// rp[129] right halo col. Direct scalar LDS for intra-warp halos (R11 form;
// shfl was slower, R12).
__device__ __forceinline__ Sums make_sums(const float* __restrict__ rp,
                                          int lane, int w) {
    float4 v = *reinterpret_cast<const float4*>(rp + 4 * lane);   // LDS.128
    float e0 = (lane == 0)  ? ((w > 0) ? rp[128] : 0.f) : rp[4 * lane - 1];
    float e5 = (lane == 31) ? ((w < 7) ? rp[129] : 0.f) : rp[4 * lane + 4];
    Sums s;
    s.t[0] = e0  + v.x + v.y;  s.g[0] = s.t[0] + v.x;
    s.t[1] = v.x + v.y + v.z;  s.g[1] = s.t[1] + v.y;
    s.t[2] = v.y + v.z + v.w;  s.g[2] = s.t[2] + v.z;
    s.t[3] = v.z + v.w + e5;   s.g[3] = s.t[3] + v.w;
    return s;
}

__device__ __forceinline__ Sums zero_sums() {
    Sums s;
    #pragma unroll
    for (int j = 0; j < 4; ++j) { s.t[j] = 0.f; s.g[j] = 0.f; }
    return s;
}

__device__ __forceinline__ float4 compute_row(const Sums& A, const Sums& B,
                                              const Sums& C) {
    float res[4];
    #pragma unroll
    for (int j = 0; j < 4; ++j) {
        float sum9 = A.t[j] + B.t[j] + C.t[j];            // 0..9 exact
        float gsum = fmaf(2.f, B.g[j], A.g[j] + C.g[j]);  // 0..16 exact
        float cen  = B.g[j] - B.t[j];                     // 0 or 1
        float qual = fmaf(6.f, cen, sum9);                // >=10 <=> qualify
        float adj  = (qual > 9.5f) ? 0.6f : 0.f;
        res[j] = (gsum + adj > 8.5f) ? 1.f : 0.f;
    }
    return make_float4(res[0], res[1], res[2], res[3]);
}

__global__ void __launch_bounds__(THREADS, 5)
edge_smooth_kernel(const float* __restrict__ in, float* __restrict__ out) {
    __shared__ float buf[4][2][8][ROWF];                  // 33792 B

    const int img  = blockIdx.y;
    const int r0   = blockIdx.x * RPB;
    const int tid  = threadIdx.x;
    const int w    = tid >> 5;
    const int lane = tid & 31;
    const int colm = w * 128 + lane * 4;                  // thread's main col

    const float* gimg = in + (size_t)img * IMG_H * IMG_W;
    const float* gm   = gimg + colm;                      // main src (per row)
    const float* gl   = gimg + w * 128 - 1;               // left halo col
    const float* gr   = gimg + w * 128 + 128;             // right halo col
    float*       po   = out + ((size_t)img * IMG_H + r0) * IMG_W + colm;

    unsigned sw = (unsigned)__cvta_generic_to_shared(&buf[0][0][w][0]);
    unsigned st = sw + (unsigned)lane * 16u;

    const bool doL = (lane == 0) && (w > 0);
    const bool doR = (lane == 1) && (w < 7);

    // Issue one pair (2 rows) into ring slot pair&3. Rows clamped; over-
    // fetched edge rows are never consumed.
    auto issue_pair = [&](int pair) {
        int row0 = min(max(r0 - 1 + 2 * pair, 0), IMG_H - 1);
        int row1 = min(r0 + 2 * pair, IMG_H - 1);
        unsigned o = (unsigned)(pair & 3) * PAIR_B;
        const float* s0 = gm + (size_t)row0 * IMG_W;
        const float* s1 = gm + (size_t)row1 * IMG_W;
        cp16(st + o,         s0);
        cp16(st + o + ROW_B, s1);
        if (doL) {
            cp4(sw + o + 512,         gl + (size_t)row0 * IMG_W);
            cp4(sw + o + ROW_B + 512, gl + (size_t)row1 * IMG_W);
        }
        if (doR) {
            cp4(sw + o + 516,         gr + (size_t)row0 * IMG_W);
            cp4(sw + o + ROW_B + 516, gr + (size_t)row1 * IMG_W);
        }
    };

    // Prologue: pairs 0,1,2 in flight (3 groups).
    issue_pair(0); CP_COMMIT();
    issue_pair(1); CP_COMMIT();
    issue_pair(2); CP_COMMIT();

    // Prime (pair 0): A = row r0-1 (zeros at image top), B = row r0.
    CP_WAIT2(); __syncwarp();
    issue_pair(3); CP_COMMIT();
    Sums A = (r0 > 0) ? make_sums(&buf[0][0][w][0], lane, w) : zero_sums();
    Sums B = make_sums(&buf[0][1][w][0], lane, w);

    // Steady state: consume pairs 1..NPAIRS-2.
    for (int i = 1; i <= NPAIRS - 2; ++i) {
        CP_WAIT2(); __syncwarp();
        if (i + 3 < NPAIRS) issue_pair(i + 3);
        CP_COMMIT();

        const int s = i & 3;
        Sums C = make_sums(&buf[s][0][w][0], lane, w);
        Sums D = make_sums(&buf[s][1][w][0], lane, w);

        *reinterpret_cast<float4*>(po)         = compute_row(A, B, C);
        *reinterpret_cast<float4*>(po + IMG_W) = compute_row(B, C, D);
        po += 2 * IMG_W;

        A = C; B = D;
    }

    // Epilogue (pair NPAIRS-1): bottom row r0+RPB is zeros at image bottom.
    CP_WAIT2(); __syncwarp();
    {
        const int s = (NPAIRS - 1) & 3;
        Sums C = make_sums(&buf[s][0][w][0], lane, w);
        Sums D = (r0 + RPB < IMG_H) ? make_sums(&buf[s][1][w][0], lane, w)
                                    : zero_sums();
        *reinterpret_cast<float4*>(po)         = compute_row(A, B, C);
        *reinterpret_cast<float4*>(po + IMG_W) = compute_row(B, C, D);
    }
}

extern "C" void kernel_launch(void* const* d_in, const int* in_sizes, int n_in,
                              void* d_out, int out_size) {
    const float* mask = (const float*)d_in[0];   // (B,C,1024,1024) f32
    float*       out  = (float*)d_out;

    int n_imgs = in_sizes[0] / (IMG_H * IMG_W);  // B*C

    dim3 grid(IMG_H / RPB, n_imgs);
    dim3 block(THREADS);
    edge_smooth_kernel<<<grid, block>>>(mask, out);
}

// round 14
// speedup vs baseline: 1.0465x; 1.0465x over previous
#include <cuda_runtime.h>

// BinaryMaskEdgeSmoothing, R14: R11 skeleton + LDS.64 halos + 6-pair ring +
// fully unrolled steady loop.
//
// R12 (shuffle halos) and R13 (warp-private rings) both REGRESSED vs R11 —
// the block-wide pair barrier is not the binder. R14 keeps R11's structure
// and fixes measured inefficiencies inside it:
//  (1) halo loads: LDS.32 at stride 16B was 4-way bank conflicted (4 phases);
//      8B-aligned LDS.64 at x0-2/.y and x0+4/.x is conflict-free (2 phases).
//  (2) ring 4 -> 6 pairs (48KB smem), wait_group(3): 4 pairs (32KB) in
//      flight per block, 128KB/SM.
//  (3) steady loop (7 iters, compile-time) fully unrolled: slot indices and
//      row offsets become immediates.
//
// Rule (verified rel_err = 0.0 since R4; binary inputs make sum9 and
// gsum = 16*blur exact small ints in f32):
//     out = (gsum >= 9) || (gsum == 8 && cen == 1 && sum9 >= 4)
// via: qual = 6*cen + sum9; adj = qual>9.5 ? 0.6 : 0; out = gsum+adj > 8.5.

#define IMG_W   1024
#define IMG_H   1024
#define RPB     16                // output rows per block
#define THREADS 256               // 4 cols per thread
#define NPAIRS  ((RPB + 2) / 2)   // 9 input pairs: rows r0-1 .. r0+RPB
#define STAGES  6                 // ring slots (pairs)
#define ROW_B   (IMG_W * 4)
#define PAIR_B  (2 * ROW_B)

struct Sums { float t[4], g[4]; };

#define CP_COMMIT() asm volatile("cp.async.commit_group;")
#define CP_WAIT3()  asm volatile("cp.async.wait_group 3;")
#define CP_WAIT0()  asm volatile("cp.async.wait_group 0;")

__device__ __forceinline__ void cp16(unsigned dst, const float* src) {
    asm volatile("cp.async.cg.shared.global [%0], [%1], 16;" ::
                 "r"(dst), "l"(src));
}

__device__ __forceinline__ Sums make_sums(const float* __restrict__ rp,
                                          int x0, bool hl, bool hr) {
    float4 v = *reinterpret_cast<const float4*>(rp + x0);     // LDS.128
    float e0 = 0.f, e5 = 0.f;
    if (hl) { float2 L = *reinterpret_cast<const float2*>(rp + x0 - 2); e0 = L.y; }
    if (hr) { float2 R = *reinterpret_cast<const float2*>(rp + x0 + 4); e5 = R.x; }
    Sums s;
    s.t[0] = e0  + v.x + v.y;  s.g[0] = s.t[0] + v.x;
    s.t[1] = v.x + v.y + v.z;  s.g[1] = s.t[1] + v.y;
    s.t[2] = v.y + v.z + v.w;  s.g[2] = s.t[2] + v.z;
    s.t[3] = v.z + v.w + e5;   s.g[3] = s.t[3] + v.w;
    return s;
}

__device__ __forceinline__ Sums zero_sums() {
    Sums s;
    #pragma unroll
    for (int j = 0; j < 4; ++j) { s.t[j] = 0.f; s.g[j] = 0.f; }
    return s;
}

__device__ __forceinline__ float4 compute_row(const Sums& A, const Sums& B,
                                              const Sums& C) {
    float res[4];
    #pragma unroll
    for (int j = 0; j < 4; ++j) {
        float sum9 = A.t[j] + B.t[j] + C.t[j];            // 0..9 exact
        float gsum = fmaf(2.f, B.g[j], A.g[j] + C.g[j]);  // 0..16 exact
        float cen  = B.g[j] - B.t[j];                     // 0 or 1
        float qual = fmaf(6.f, cen, sum9);                // >=10 <=> qualify
        float adj  = (qual > 9.5f) ? 0.6f : 0.f;
        res[j] = (gsum + adj > 8.5f) ? 1.f : 0.f;
    }
    return make_float4(res[0], res[1], res[2], res[3]);
}

__global__ void __launch_bounds__(THREADS, 4)
edge_smooth_kernel(const float* __restrict__ in, float* __restrict__ out) {
    __shared__ float buf[STAGES][2][IMG_W];               // 48KB ring

    const int img = blockIdx.y;
    const int r0  = blockIdx.x * RPB;
    const int tid = threadIdx.x;
    const int x0  = tid * 4;
    const bool hl = (x0 > 0);
    const bool hr = (x0 + 4 < IMG_W);

    const float* gsrc = in + (size_t)img * IMG_H * IMG_W + x0;
    float*       po   = out + ((size_t)img * IMG_H + r0) * IMG_W + x0;

    unsigned sb = (unsigned)__cvta_generic_to_shared(&buf[0][0][0]) + tid * 16u;

    // Issue one pair (rows r0-1+2p, r0+2p; clamped — over-fetched edge rows
    // are never consumed) into ring slot p % STAGES.
    auto issue_pair = [&](int p) {
        int row0 = min(max(r0 - 1 + 2 * p, 0), IMG_H - 1);
        int row1 = min(r0 + 2 * p, IMG_H - 1);
        unsigned dst = sb + (unsigned)(p % STAGES) * PAIR_B;
        cp16(dst,         gsrc + (size_t)row0 * IMG_W);
        cp16(dst + ROW_B, gsrc + (size_t)row1 * IMG_W);
    };

    // Prologue: pairs 0..3 in flight (4 groups).
    issue_pair(0); CP_COMMIT();
    issue_pair(1); CP_COMMIT();
    issue_pair(2); CP_COMMIT();
    issue_pair(3); CP_COMMIT();

    // Prime (pair 0): A = row r0-1 (zeros at image top), B = row r0.
    CP_WAIT3(); __syncthreads();
    issue_pair(4); CP_COMMIT();
    Sums A = (r0 > 0) ? make_sums(buf[0][0], x0, hl, hr) : zero_sums();
    Sums B = make_sums(buf[0][1], x0, hl, hr);

    // Steady state: consume pairs 1..7; issue pairs 5..8. Fully unrolled.
    #pragma unroll
    for (int i = 1; i <= NPAIRS - 2; ++i) {
        CP_WAIT3(); __syncthreads();
        if (i + 4 < NPAIRS) issue_pair(i + 4);
        CP_COMMIT();                         // empty groups keep count uniform

        const int s = i % STAGES;
        Sums C = make_sums(buf[s][0], x0, hl, hr);
        Sums D = make_sums(buf[s][1], x0, hl, hr);

        *reinterpret_cast<float4*>(po)         = compute_row(A, B, C);
        *reinterpret_cast<float4*>(po + IMG_W) = compute_row(B, C, D);
        po += 2 * IMG_W;

        A = C; B = D;
    }

    // Epilogue (pair 8): bottom row r0+RPB is zeros at image bottom.
    CP_WAIT0(); __syncthreads();
    {
        const int s = (NPAIRS - 1) % STAGES;
        Sums C = make_sums(buf[s][0], x0, hl, hr);
        Sums D = (r0 + RPB < IMG_H) ? make_sums(buf[s][1], x0, hl, hr)
                                    : zero_sums();
        *reinterpret_cast<float4*>(po)         = compute_row(A, B, C);
        *reinterpret_cast<float4*>(po + IMG_W) = compute_row(B, C, D);
    }
}

extern "C" void kernel_launch(void* const* d_in, const int* in_sizes, int n_in,
                              void* d_out, int out_size) {
    const float* mask = (const float*)d_in[0];   // (B,C,1024,1024) f32
    float*       out  = (float*)d_out;

    int n_imgs = in_sizes[0] / (IMG_H * IMG_W);  // B*C

    dim3 grid(IMG_H / RPB, n_imgs);
    dim3 block(THREADS);
    edge_smooth_kernel<<<grid, block>>>(mask, out);
}

// round 15
// speedup vs baseline: 1.0492x; 1.0026x over previous
#include <cuda_runtime.h>

// BinaryMaskEdgeSmoothing, R15: R14 skeleton, occupancy 5, streaming stores,
// L2-prefetch cp.async.
//
// Byte accounting across R9-R14: DRAM traffic ~= the logical 512MB minimum at
// ~76% of spec BW, with barriers/issue/LSU/smem all <=50%. Remaining levers
// are stream smoothness (occupancy) and cache policy:
//  (1) 5-pair ring (40KB) + launch_bounds(256,5): occ 47.6 -> ~59%.
//  (2) __stcs (evict-first) stores: write stream never re-read; keep L2 for
//      the read/halo stream.
//  (3) cp.async.cg with L2::256B prefetch: coarser read granularity at LTS.
//
// Rule (verified rel_err = 0.0 since R4; binary inputs make sum9 and
// gsum = 16*blur exact small ints in f32):
//     out = (gsum >= 9) || (gsum == 8 && cen == 1 && sum9 >= 4)
// via: qual = 6*cen + sum9; adj = qual>9.5 ? 0.6 : 0; out = gsum+adj > 8.5.

#define IMG_W   1024
#define IMG_H   1024
#define RPB     16                // output rows per block
#define THREADS 256               // 4 cols per thread
#define NPAIRS  ((RPB + 2) / 2)   // 9 input pairs: rows r0-1 .. r0+RPB
#define STAGES  5                 // ring slots (pairs) -> 40KB smem
#define ROW_B   (IMG_W * 4)
#define PAIR_B  (2 * ROW_B)

struct Sums { float t[4], g[4]; };

#define CP_COMMIT() asm volatile("cp.async.commit_group;")
#define CP_WAIT3()  asm volatile("cp.async.wait_group 3;")
#define CP_WAIT0()  asm volatile("cp.async.wait_group 0;")

__device__ __forceinline__ void cp16(unsigned dst, const float* src) {
    asm volatile("cp.async.cg.shared.global.L2::256B [%0], [%1], 16;" ::
                 "r"(dst), "l"(src));
}

__device__ __forceinline__ Sums make_sums(const float* __restrict__ rp,
                                          int x0, bool hl, bool hr) {
    float4 v = *reinterpret_cast<const float4*>(rp + x0);     // LDS.128
    float e0 = 0.f, e5 = 0.f;
    if (hl) { float2 L = *reinterpret_cast<const float2*>(rp + x0 - 2); e0 = L.y; }
    if (hr) { float2 R = *reinterpret_cast<const float2*>(rp + x0 + 4); e5 = R.x; }
    Sums s;
    s.t[0] = e0  + v.x + v.y;  s.g[0] = s.t[0] + v.x;
    s.t[1] = v.x + v.y + v.z;  s.g[1] = s.t[1] + v.y;
    s.t[2] = v.y + v.z + v.w;  s.g[2] = s.t[2] + v.z;
    s.t[3] = v.z + v.w + e5;   s.g[3] = s.t[3] + v.w;
    return s;
}

__device__ __forceinline__ Sums zero_sums() {
    Sums s;
    #pragma unroll
    for (int j = 0; j < 4; ++j) { s.t[j] = 0.f; s.g[j] = 0.f; }
    return s;
}

__device__ __forceinline__ float4 compute_row(const Sums& A, const Sums& B,
                                              const Sums& C) {
    float res[4];
    #pragma unroll
    for (int j = 0; j < 4; ++j) {
        float sum9 = A.t[j] + B.t[j] + C.t[j];            // 0..9 exact
        float gsum = fmaf(2.f, B.g[j], A.g[j] + C.g[j]);  // 0..16 exact
        float cen  = B.g[j] - B.t[j];                     // 0 or 1
        float qual = fmaf(6.f, cen, sum9);                // >=10 <=> qualify
        float adj  = (qual > 9.5f) ? 0.6f : 0.f;
        res[j] = (gsum + adj > 8.5f) ? 1.f : 0.f;
    }
    return make_float4(res[0], res[1], res[2], res[3]);
}

__global__ void __launch_bounds__(THREADS, 5)
edge_smooth_kernel(const float* __restrict__ in, float* __restrict__ out) {
    __shared__ float buf[STAGES][2][IMG_W];               // 40KB ring

    const int img = blockIdx.y;
    const int r0  = blockIdx.x * RPB;
    const int tid = threadIdx.x;
    const int x0  = tid * 4;
    const bool hl = (x0 > 0);
    const bool hr = (x0 + 4 < IMG_W);

    const float* gsrc = in + (size_t)img * IMG_H * IMG_W + x0;
    float*       po   = out + ((size_t)img * IMG_H + r0) * IMG_W + x0;

    unsigned sb = (unsigned)__cvta_generic_to_shared(&buf[0][0][0]) + tid * 16u;

    // Issue one pair (rows r0-1+2p, r0+2p; clamped — over-fetched edge rows
    // are never consumed) into ring slot p % STAGES.
    auto issue_pair = [&](int p) {
        int row0 = min(max(r0 - 1 + 2 * p, 0), IMG_H - 1);
        int row1 = min(r0 + 2 * p, IMG_H - 1);
        unsigned dst = sb + (unsigned)(p % STAGES) * PAIR_B;
        cp16(dst,         gsrc + (size_t)row0 * IMG_W);
        cp16(dst + ROW_B, gsrc + (size_t)row1 * IMG_W);
    };

    // Prologue: pairs 0..3 in flight (4 groups).
    issue_pair(0); CP_COMMIT();
    issue_pair(1); CP_COMMIT();
    issue_pair(2); CP_COMMIT();
    issue_pair(3); CP_COMMIT();

    // Prime (pair 0): A = row r0-1 (zeros at image top), B = row r0.
    CP_WAIT3(); __syncthreads();
    issue_pair(4); CP_COMMIT();
    Sums A = (r0 > 0) ? make_sums(buf[0][0], x0, hl, hr) : zero_sums();
    Sums B = make_sums(buf[0][1], x0, hl, hr);

    // Steady state: consume pairs 1..7; issue pairs 5..8.
    // Slot safety: pair i+4 writes slot (i-1)%5, whose consumption (iter i-1)
    // is sealed by this iteration's barrier before the issue.
    for (int i = 1; i <= NPAIRS - 2; ++i) {
        CP_WAIT3(); __syncthreads();
        if (i + 4 < NPAIRS) issue_pair(i + 4);
        CP_COMMIT();                         // empty groups keep count uniform

        const int s = i % STAGES;
        Sums C = make_sums(buf[s][0], x0, hl, hr);
        Sums D = make_sums(buf[s][1], x0, hl, hr);

        __stcs(reinterpret_cast<float4*>(po),         compute_row(A, B, C));
        __stcs(reinterpret_cast<float4*>(po + IMG_W), compute_row(B, C, D));
        po += 2 * IMG_W;

        A = C; B = D;
    }

    // Epilogue (pair 8): bottom row r0+RPB is zeros at image bottom.
    CP_WAIT0(); __syncthreads();
    {
        const int s = (NPAIRS - 1) % STAGES;
        Sums C = make_sums(buf[s][0], x0, hl, hr);
        Sums D = (r0 + RPB < IMG_H) ? make_sums(buf[s][1], x0, hl, hr)
                                    : zero_sums();
        __stcs(reinterpret_cast<float4*>(po),         compute_row(A, B, C));
        __stcs(reinterpret_cast<float4*>(po + IMG_W), compute_row(B, C, D));
    }
}

extern "C" void kernel_launch(void* const* d_in, const int* in_sizes, int n_in,
                              void* d_out, int out_size) {
    const float* mask = (const float*)d_in[0];   // (B,C,1024,1024) f32
    float*       out  = (float*)d_out;

    int n_imgs = in_sizes[0] / (IMG_H * IMG_W);  // B*C

    dim3 grid(IMG_H / RPB, n_imgs);
    dim3 block(THREADS);
    edge_smooth_kernel<<<grid, block>>>(mask, out);
}

// round 16
// speedup vs baseline: 1.0519x; 1.0026x over previous
#include <cuda_runtime.h>

// BinaryMaskEdgeSmoothing, R16: R15 (occ-5, 5-pair ring, stcs, L2::256B)
// + fully unrolled steady loop + clamp-free interior issue path.
//
// R15 post-mortem: dropping R14's unroll made slot indices (% 5) runtime
// IMADs (ALU 22 -> 38%). R16 unrolls the 7-iteration steady loop so slots,
// row offsets and store pointers are immediates, and gives interior pairs a
// clamp-free issue path (only pairs 0 and 8 can touch image edges).
//
// Rule (verified rel_err = 0.0 since R4; binary inputs make sum9 and
// gsum = 16*blur exact small ints in f32):
//     out = (gsum >= 9) || (gsum == 8 && cen == 1 && sum9 >= 4)
// via: qual = 6*cen + sum9; adj = qual>9.5 ? 0.6 : 0; out = gsum+adj > 8.5.

#define IMG_W   1024
#define IMG_H   1024
#define RPB     16                // output rows per block
#define THREADS 256               // 4 cols per thread
#define NPAIRS  ((RPB + 2) / 2)   // 9 input pairs: rows r0-1 .. r0+RPB
#define STAGES  5                 // ring slots (pairs) -> 40KB smem
#define ROW_B   (IMG_W * 4)
#define PAIR_B  (2 * ROW_B)

struct Sums { float t[4], g[4]; };

#define CP_COMMIT() asm volatile("cp.async.commit_group;")
#define CP_WAIT3()  asm volatile("cp.async.wait_group 3;")
#define CP_WAIT0()  asm volatile("cp.async.wait_group 0;")

__device__ __forceinline__ void cp16(unsigned dst, const float* src) {
    asm volatile("cp.async.cg.shared.global.L2::256B [%0], [%1], 16;" ::
                 "r"(dst), "l"(src));
}

__device__ __forceinline__ Sums make_sums(const float* __restrict__ rp,
                                          int x0, bool hl, bool hr) {
    float4 v = *reinterpret_cast<const float4*>(rp + x0);     // LDS.128
    float e0 = 0.f, e5 = 0.f;
    if (hl) { float2 L = *reinterpret_cast<const float2*>(rp + x0 - 2); e0 = L.y; }
    if (hr) { float2 R = *reinterpret_cast<const float2*>(rp + x0 + 4); e5 = R.x; }
    Sums s;
    s.t[0] = e0  + v.x + v.y;  s.g[0] = s.t[0] + v.x;
    s.t[1] = v.x + v.y + v.z;  s.g[1] = s.t[1] + v.y;
    s.t[2] = v.y + v.z + v.w;  s.g[2] = s.t[2] + v.z;
    s.t[3] = v.z + v.w + e5;   s.g[3] = s.t[3] + v.w;
    return s;
}

__device__ __forceinline__ Sums zero_sums() {
    Sums s;
    #pragma unroll
    for (int j = 0; j < 4; ++j) { s.t[j] = 0.f; s.g[j] = 0.f; }
    return s;
}

__device__ __forceinline__ float4 compute_row(const Sums& A, const Sums& B,
                                              const Sums& C) {
    float res[4];
    #pragma unroll
    for (int j = 0; j < 4; ++j) {
        float sum9 = A.t[j] + B.t[j] + C.t[j];            // 0..9 exact
        float gsum = fmaf(2.f, B.g[j], A.g[j] + C.g[j]);  // 0..16 exact
        float cen  = B.g[j] - B.t[j];                     // 0 or 1
        float qual = fmaf(6.f, cen, sum9);                // >=10 <=> qualify
        float adj  = (qual > 9.5f) ? 0.6f : 0.f;
        res[j] = (gsum + adj > 8.5f) ? 1.f : 0.f;
    }
    return make_float4(res[0], res[1], res[2], res[3]);
}

__global__ void __launch_bounds__(THREADS, 5)
edge_smooth_kernel(const float* __restrict__ in, float* __restrict__ out) {
    __shared__ float buf[STAGES][2][IMG_W];               // 40KB ring

    const int img = blockIdx.y;
    const int r0  = blockIdx.x * RPB;
    const int tid = threadIdx.x;
    const int x0  = tid * 4;
    const bool hl = (x0 > 0);
    const bool hr = (x0 + 4 < IMG_W);

    const float* gsrc = in + (size_t)img * IMG_H * IMG_W + x0;
    float*       po   = out + ((size_t)img * IMG_H + r0) * IMG_W + x0;

    unsigned sb = (unsigned)__cvta_generic_to_shared(&buf[0][0][0]) + tid * 16u;

    // Interior pair issue: rows r0-1+2p, r0+2p, no clamping needed
    // (valid for pairs 1..7 on every strip: 1 <= r0-1+2p, r0+2p <= r0+14+1).
    auto issue_fast = [&](int p) {
        unsigned dst = sb + (unsigned)(p % STAGES) * PAIR_B;  // p compile-time
        const float* s0 = gsrc + (size_t)(r0 - 1 + 2 * p) * IMG_W;
        cp16(dst,         s0);
        cp16(dst + ROW_B, s0 + IMG_W);
    };
    // Edge-capable issue (pairs 0 and 8): rows clamped; over-fetched edge
    // rows are never consumed.
    auto issue_clamped = [&](int p) {
        int row0 = min(max(r0 - 1 + 2 * p, 0), IMG_H - 1);
        int row1 = min(r0 + 2 * p, IMG_H - 1);
        unsigned dst = sb + (unsigned)(p % STAGES) * PAIR_B;
        cp16(dst,         gsrc + (size_t)row0 * IMG_W);
        cp16(dst + ROW_B, gsrc + (size_t)row1 * IMG_W);
    };

    // Prologue: pairs 0..3 in flight (4 groups).
    issue_clamped(0); CP_COMMIT();
    issue_fast(1);    CP_COMMIT();
    issue_fast(2);    CP_COMMIT();
    issue_fast(3);    CP_COMMIT();

    // Prime (pair 0): A = row r0-1 (zeros at image top), B = row r0.
    CP_WAIT3(); __syncthreads();
    issue_fast(4); CP_COMMIT();
    Sums A = (r0 > 0) ? make_sums(buf[0][0], x0, hl, hr) : zero_sums();
    Sums B = make_sums(buf[0][1], x0, hl, hr);

    // Steady state: consume pairs 1..7; issue pairs 5..8. Fully unrolled so
    // slot indices / offsets are immediates. Slot safety: pair i+4 writes
    // slot (i-1)%5, sealed by this iteration's barrier.
    #pragma unroll
    for (int i = 1; i <= NPAIRS - 2; ++i) {
        CP_WAIT3(); __syncthreads();
        if (i + 4 < NPAIRS - 1)      issue_fast(i + 4);
        else if (i + 4 == NPAIRS - 1) issue_clamped(i + 4);
        CP_COMMIT();                         // empty groups keep count uniform

        const int s = i % STAGES;            // compile-time after unroll
        Sums C = make_sums(buf[s][0], x0, hl, hr);
        Sums D = make_sums(buf[s][1], x0, hl, hr);

        __stcs(reinterpret_cast<float4*>(po + (size_t)(2 * i - 2) * IMG_W),
               compute_row(A, B, C));
        __stcs(reinterpret_cast<float4*>(po + (size_t)(2 * i - 1) * IMG_W),
               compute_row(B, C, D));

        A = C; B = D;
    }

    // Epilogue (pair 8): bottom row r0+RPB is zeros at image bottom.
    CP_WAIT0(); __syncthreads();
    {
        const int s = (NPAIRS - 1) % STAGES;
        Sums C = make_sums(buf[s][0], x0, hl, hr);
        Sums D = (r0 + RPB < IMG_H) ? make_sums(buf[s][1], x0, hl, hr)
                                    : zero_sums();
        __stcs(reinterpret_cast<float4*>(po + (size_t)(RPB - 2) * IMG_W),
               compute_row(A, B, C));
        __stcs(reinterpret_cast<float4*>(po + (size_t)(RPB - 1) * IMG_W),
               compute_row(B, C, D));
    }
}

extern "C" void kernel_launch(void* const* d_in, const int* in_sizes, int n_in,
                              void* d_out, int out_size) {
    const float* mask = (const float*)d_in[0];   // (B,C,1024,1024) f32
    float*       out  = (float*)d_out;

    int n_imgs = in_sizes[0] / (IMG_H * IMG_W);  // B*C

    dim3 grid(IMG_H / RPB, n_imgs);
    dim3 block(THREADS);
    edge_smooth_kernel<<<grid, block>>>(mask, out);
}